// round 17
// baseline (speedup 1.0000x reference)
#include <cuda_runtime.h>
#include <cuda_fp16.h>
#include <math.h>

// Problem constants (fixed shapes)
#define NN 20000
#define EE 320000
#define CC 64

// ---------------- scratch (device globals; no allocation allowed) ----------------
__device__ __align__(16) __half g_s[NN * CC];           // up-projected scalars (fp16)
__device__ __align__(16) __half g_v[NN * CC * 3];       // up-projected vectors (fp16)
__device__ __align__(16) float g_skip_s[NN * 2 * CC];   // skip_s[n][o]
__device__ __align__(16) float g_skip_v[NN * CC * 3];   // skip_v[n][o][m]
__device__ __align__(16) float g_agg_s[NN * 2 * CC];    // agg_s raw sums
__device__ __align__(16) float g_agg_v[NN * 3 * 2 * CC];// agg_v[n][m][c2] raw sums
__device__ __align__(16) __half g_mix[EE * 256];        // per-edge MLP output (fp16)
__device__ __align__(16) float g_y[EE * 4];             // per-edge sqrt(3)*vhat (w=0)

__device__ __forceinline__ float swishf(float x) { return x / (1.0f + __expf(-x)); }

__device__ __forceinline__ void red4(float* p, float a, float b, float c, float d) {
    asm volatile("red.global.add.v4.f32 [%0], {%1,%2,%3,%4};"
                 :: "l"(p), "f"(a), "f"(b), "f"(c), "f"(d) : "memory");
}

// ---- packed f32x2 helpers (Blackwell FFMA2 path) ----
__device__ __forceinline__ unsigned long long dup2(float a) {
    unsigned long long r;
    asm("mov.b64 %0, {%1,%1};" : "=l"(r) : "f"(a));
    return r;
}
__device__ __forceinline__ unsigned long long ffma2(unsigned long long a,
                                                    unsigned long long b,
                                                    unsigned long long c) {
    unsigned long long d;
    asm("fma.rn.f32x2 %0, %1, %2, %3;" : "=l"(d) : "l"(a), "l"(b), "l"(c));
    return d;
}
__device__ __forceinline__ float2 unpack2(unsigned long long v) {
    float2 f;
    asm("mov.b64 {%0,%1}, %2;" : "=f"(f.x), "=f"(f.y) : "l"(v));
    return f;
}

// ---- ldmatrix / mma.sync (HMMA, fp16 in, fp32 acc) ----
__device__ __forceinline__ void ldsm_x4(unsigned& r0, unsigned& r1, unsigned& r2, unsigned& r3,
                                        unsigned addr) {
    asm volatile("ldmatrix.sync.aligned.m8n8.x4.shared.b16 {%0,%1,%2,%3}, [%4];"
                 : "=r"(r0), "=r"(r1), "=r"(r2), "=r"(r3) : "r"(addr));
}
__device__ __forceinline__ void ldsm_x2_trans(unsigned& r0, unsigned& r1, unsigned addr) {
    asm volatile("ldmatrix.sync.aligned.m8n8.x2.trans.shared.b16 {%0,%1}, [%2];"
                 : "=r"(r0), "=r"(r1) : "r"(addr));
}
__device__ __forceinline__ void mma16816(float& c0, float& c1, float& c2, float& c3,
                                         unsigned a0, unsigned a1, unsigned a2, unsigned a3,
                                         unsigned b0, unsigned b1) {
    asm volatile("mma.sync.aligned.m16n8k16.row.col.f32.f16.f16.f32 "
                 "{%0,%1,%2,%3}, {%4,%5,%6,%7}, {%8,%9}, {%0,%1,%2,%3};"
                 : "+f"(c0), "+f"(c1), "+f"(c2), "+f"(c3)
                 : "r"(a0), "r"(a1), "r"(a2), "r"(a3), "r"(b0), "r"(b1));
}

// ---------------- kernel: zero aggregation buffers ----------------
__global__ void k_zero() {
    float4 z = make_float4(0.f, 0.f, 0.f, 0.f);
    int n1 = NN * 2 * CC / 4;
    for (int i = blockIdx.x * blockDim.x + threadIdx.x; i < n1; i += gridDim.x * blockDim.x)
        reinterpret_cast<float4*>(g_agg_s)[i] = z;
    int n2 = NN * 6 * CC / 4;
    for (int i = blockIdx.x * blockDim.x + threadIdx.x; i < n2; i += gridDim.x * blockDim.x)
        reinterpret_cast<float4*>(g_agg_v)[i] = z;
}

// ---------------- kernel: node up-projection (fp16 outputs) ----------------
__global__ void __launch_bounds__(256) k_up(const float* __restrict__ scal,
                                            const float* __restrict__ nvec,
                                            const float* __restrict__ Wus,
                                            const float* __restrict__ Wuv) {
    extern __shared__ float sm[];
    float* sWs = sm;          // 64*64
    float* sWv = sm + 4096;   // 64*64
    float* sBuf = sm + 8192;  // 8 warps * 256
    int tid = threadIdx.x, wid = tid >> 5, l = tid & 31;
    for (int i = tid; i < 4096; i += 256) { sWs[i] = Wus[i]; sWv[i] = Wuv[i]; }
    __syncthreads();
    float* sc = sBuf + wid * 256;
    float* vb = sc + 64;
    int nwarp = gridDim.x * 8;
    for (int n = blockIdx.x * 8 + wid; n < NN; n += nwarp) {
        sc[l] = scal[n * 64 + l];
        sc[l + 32] = scal[n * 64 + l + 32];
#pragma unroll
        for (int q = 0; q < 6; q++) vb[l + q * 32] = nvec[n * 192 + l + q * 32];
        __syncwarp();
        float a0 = 0.f, a1 = 0.f;
#pragma unroll
        for (int k = 0; k < 64; k++) {
            float a = sc[k];
            a0 = fmaf(a, sWs[k * 64 + l], a0);
            a1 = fmaf(a, sWs[k * 64 + l + 32], a1);
        }
        g_s[n * 64 + l] = __float2half(a0);
        g_s[n * 64 + l + 32] = __float2half(a1);
        float v0[3] = {0.f, 0.f, 0.f}, v1[3] = {0.f, 0.f, 0.f};
#pragma unroll
        for (int k = 0; k < 64; k++) {
            float w0 = sWv[k * 64 + l], w1 = sWv[k * 64 + l + 32];
#pragma unroll
            for (int m = 0; m < 3; m++) {
                float a = vb[k * 3 + m];
                v0[m] = fmaf(a, w0, v0[m]);
                v1[m] = fmaf(a, w1, v1[m]);
            }
        }
#pragma unroll
        for (int m = 0; m < 3; m++) {
            g_v[n * 192 + l * 3 + m] = __float2half(v0[m]);
            g_v[n * 192 + (l + 32) * 3 + m] = __float2half(v1[m]);
        }
        __syncwarp();
    }
}

// ---------------- kernel: per-species skip projections ----------------
__global__ void __launch_bounds__(256) k_skip(const float* __restrict__ scal,
                                              const float* __restrict__ nvec,
                                              const int* __restrict__ specie,
                                              const float* __restrict__ Wss,
                                              const float* __restrict__ Wsv) {
    extern __shared__ float sm[];
    float* sS = sm;            // 32768
    float* sV = sm + 32768;    // 16384
    float* sBuf = sm + 49152;  // 8 * 256
    int tid = threadIdx.x, wid = tid >> 5, l = tid & 31;
    for (int i = tid; i < 32768; i += 256) sS[i] = Wss[i];
    for (int i = tid; i < 16384; i += 256) sV[i] = Wsv[i];
    __syncthreads();
    float* sc = sBuf + wid * 256;
    float* vb = sc + 64;
    int nwarp = gridDim.x * 8;
    for (int n = blockIdx.x * 8 + wid; n < NN; n += nwarp) {
        sc[l] = scal[n * 64 + l];
        sc[l + 32] = scal[n * 64 + l + 32];
#pragma unroll
        for (int q = 0; q < 6; q++) vb[l + q * 32] = nvec[n * 192 + l + q * 32];
        __syncwarp();
        int sp = specie[n];
        const float* ws = sS + sp * 8192;
        const float* wv = sV + sp * 4096;
        float a0 = 0.f, a1 = 0.f, a2 = 0.f, a3 = 0.f;
#pragma unroll
        for (int k = 0; k < 64; k++) {
            float x = sc[k];
            const float* w = ws + k * 128;
            a0 = fmaf(x, w[l], a0);
            a1 = fmaf(x, w[l + 32], a1);
            a2 = fmaf(x, w[l + 64], a2);
            a3 = fmaf(x, w[l + 96], a3);
        }
        g_skip_s[n * 128 + l] = a0;
        g_skip_s[n * 128 + l + 32] = a1;
        g_skip_s[n * 128 + l + 64] = a2;
        g_skip_s[n * 128 + l + 96] = a3;
        float v0[3] = {0.f, 0.f, 0.f}, v1[3] = {0.f, 0.f, 0.f};
#pragma unroll
        for (int k = 0; k < 64; k++) {
            float w0 = wv[k * 64 + l], w1 = wv[k * 64 + l + 32];
#pragma unroll
            for (int m = 0; m < 3; m++) {
                float a = vb[k * 3 + m];
                v0[m] = fmaf(a, w0, v0[m]);
                v1[m] = fmaf(a, w1, v1[m]);
            }
        }
#pragma unroll
        for (int m = 0; m < 3; m++) {
            g_skip_v[n * 192 + l * 3 + m] = v0[m];
            g_skip_v[n * 192 + (l + 32) * 3 + m] = v1[m];
        }
        __syncwarp();
    }
}

// ---------------- kernel: edge MLP -> g_mix (fp16), g_y ----------------
// Phases 1-3 as R16 (fp32 FFMA/FFMA2). Phase 3 epilogue writes h1 as fp16 into
// an ldmatrix-ready buffer (pitch 72 halves = 144B, conflict-free). Phase 4 is
// tensorized: ldmatrix + mma.sync.m16n8k16 f16xf16->f32, W2 staged in smem fp16
// (pitch 264 halves = 528B). Each warp owns e-tile (wid&3) and j-half (wid>>2).
// smem floats layout:
//   sW0  @0      (512)
//   sW1  @512    (4096)
//   sH   @4608   (4160)   fp32 h0 (phase 2 -> 3)
//   sF   @8768   (576)
//   W2h  @9344   (8448 f = 16896 halves: 64 x 264)
//   sHh  @17792  (2304 f = 4608 halves: 64 x 72)
// total 20096 floats = 80384 B -> 2 blocks/SM
#define MLP_SMEM_FLOATS 20096

__global__ void __launch_bounds__(256, 2) k_mlp(const float* __restrict__ vectors,
                                                const float* __restrict__ W0,
                                                const float* __restrict__ W1,
                                                const float* __restrict__ W2) {
    extern __shared__ float sm[];
    float* sW0 = sm;
    float* sW1 = sm + 512;
    float* sH  = sm + 4608;
    float* sF  = sm + 8768;
    __half* W2h = reinterpret_cast<__half*>(sm + 9344);
    __half* sHh = reinterpret_cast<__half*>(sm + 17792);

    int tid = threadIdx.x;
    for (int i = tid; i < 512; i += 256) sW0[i] = W0[i];
    for (int i = tid; i < 4096; i += 256) sW1[i] = W1[i];
    for (int i = tid; i < 16384; i += 256) {
        int k = i >> 8, j = i & 255;
        W2h[k * 264 + j] = __float2half(W2[i]);
    }
    __syncthreads();

    const int og = tid >> 3;  // 0..31
    const int eg = tid & 7;   // 0..7
    const int wid = tid >> 5, lane = tid & 31;
    unsigned sHh_u32 = (unsigned)__cvta_generic_to_shared(sHh);
    unsigned W2h_u32 = (unsigned)__cvta_generic_to_shared(W2h);
    const float SQRT2 = 1.41421356237309515f;
    const float SQRT3 = 1.73205080756887729f;
    const float PI = 3.14159265358979323846f;

    int ntile = EE / 64;
    for (int t = blockIdx.x; t < ntile; t += gridDim.x) {
        int e0 = t * 64;
        // ---- phase 1: per-edge features (threads 0..63) ----
        if (tid < 64) {
            int e = e0 + tid;
            float vx = vectors[e * 3 + 0];
            float vy = vectors[e * 3 + 1];
            float vz = vectors[e * 3 + 2];
            float x = sqrtf(vx * vx + vy * vy + vz * vz);
            float sx = (x == 0.f) ? 1.f : x;
            float inv = 1.f / sx;
            float4 yv = make_float4(SQRT3 * vx * inv, SQRT3 * vy * inv, SQRT3 * vz * inv, 0.f);
            *reinterpret_cast<float4*>(g_y + e * 4) = yv;
            float u = fminf(x, 1.f);
            float u2 = u * u, u3 = u2 * u, u6 = u3 * u3, u7 = u6 * u, u8 = u7 * u;
            float env = (x < 1.f) ? (1.f - 28.f * u6 + 48.f * u7 - 21.f * u8) : 0.f;
            float s1, c1;
            sincosf(PI * x, &s1, &c1);
            float pref = SQRT2 * inv * env;
            float sn = s1, cn = c1;
            sF[tid * 9 + 0] = pref * sn;
#pragma unroll
            for (int b = 1; b < 8; b++) {
                float sn1 = sn * c1 + cn * s1;
                float cn1 = cn * c1 - sn * s1;
                sn = sn1; cn = cn1;
                sF[tid * 9 + b] = pref * sn;
            }
        }
        __syncthreads();

        // ---- phase 2: h0 = swish(feat @ W0) ----
        {
            float a0[8], a1[8];
#pragma unroll
            for (int i = 0; i < 8; i++) { a0[i] = 0.f; a1[i] = 0.f; }
#pragma unroll
            for (int b = 0; b < 8; b++) {
                float w0 = sW0[b * 64 + og];
                float w1 = sW0[b * 64 + og + 32];
#pragma unroll
                for (int i = 0; i < 8; i++) {
                    float f = sF[(eg + 8 * i) * 9 + b];
                    a0[i] = fmaf(f, w0, a0[i]);
                    a1[i] = fmaf(f, w1, a1[i]);
                }
            }
#pragma unroll
            for (int i = 0; i < 8; i++) {
                sH[(eg + 8 * i) * 65 + og] = swishf(a0[i]);
                sH[(eg + 8 * i) * 65 + og + 32] = swishf(a1[i]);
            }
        }
        __syncthreads();

        // ---- phase 3: h1 = swish(h0 @ W1), FFMA2; epilogue -> fp16 sHh ----
        {
            unsigned long long acc[8];
#pragma unroll
            for (int i = 0; i < 8; i++) acc[i] = 0ULL;
            const unsigned long long* w1p =
                reinterpret_cast<const unsigned long long*>(sW1 + 2 * og);
#pragma unroll 2
            for (int k = 0; k < 64; k++) {
                unsigned long long wp = w1p[k * 32];
#pragma unroll
                for (int i = 0; i < 8; i++) {
                    unsigned long long ad = dup2(sH[(eg + 8 * i) * 65 + k]);
                    acc[i] = ffma2(ad, wp, acc[i]);
                }
            }
#pragma unroll
            for (int i = 0; i < 8; i++) {
                float2 f = unpack2(acc[i]);
                __half2 h = __floats2half2_rn(swishf(f.x), swishf(f.y));
                *reinterpret_cast<__half2*>(sHh + (eg + 8 * i) * 72 + 2 * og) = h;
            }
        }
        __syncthreads();

        // ---- phase 4: mix = h1 @ W2 via ldmatrix + mma.sync (fp32 acc) ----
        {
            int et = wid & 3;                 // e-tile: edges [16*et, 16*et+16)
            int jbase = (wid >> 2) * 128;     // j-half
            unsigned aAddr = sHh_u32 +
                (unsigned)((et * 16 + (lane & 15)) * 144 + (lane >> 4) * 16);
            unsigned a[4][4];
#pragma unroll
            for (int kc = 0; kc < 4; kc++)
                ldsm_x4(a[kc][0], a[kc][1], a[kc][2], a[kc][3], aAddr + kc * 32);
            int row = lane >> 2, colp = (lane & 3) * 2;
            int e_lo = e0 + et * 16 + row;
#pragma unroll
            for (int jt8 = 0; jt8 < 16; jt8++) {
                int jt = jbase + jt8 * 8;
                float c0 = 0.f, c1 = 0.f, c2 = 0.f, c3 = 0.f;
                unsigned bAddr = W2h_u32 + (unsigned)((lane & 15) * 528 + jt * 2);
#pragma unroll
                for (int kc = 0; kc < 4; kc++) {
                    unsigned b0, b1;
                    ldsm_x2_trans(b0, b1, bAddr + kc * 16 * 528);
                    mma16816(c0, c1, c2, c3,
                             a[kc][0], a[kc][1], a[kc][2], a[kc][3], b0, b1);
                }
                *reinterpret_cast<__half2*>(g_mix + (size_t)e_lo * 256 + jt + colp) =
                    __floats2half2_rn(c0, c1);
                *reinterpret_cast<__half2*>(g_mix + (size_t)(e_lo + 8) * 256 + jt + colp) =
                    __floats2half2_rn(c2, c3);
            }
        }
        __syncthreads();  // protect sF/sH/sHh before next tile
    }
}

// ---------------- kernel: gather + message + scatter (warp-per-edge, unchanged) ----------------
__global__ void __launch_bounds__(256) k_scatter(const int* __restrict__ senders,
                                                 const int* __restrict__ receivers) {
    __shared__ float sb[8][520];  // per warp: S[64] V[192] M[256] Y[4] (+pad)
    int tid = threadIdx.x;
    int w = tid >> 5, l = tid & 31;
    const float INV_SQRT3 = 0.57735026918962576f;
    float* S = sb[w];
    float* V = S + 64;
    float* M = V + 192;
    float* Yp = M + 256;
    int nwarp = gridDim.x * 8;
    for (int e = blockIdx.x * 8 + w; e < EE; e += nwarp) {
        int snd = senders[e];
        int rcv = receivers[e];
#pragma unroll
        for (int half = 0; half < 2; half++) {
            int base = half * 128 + l * 4;
            union { uint2 u; __half2 h[2]; } pk;
            pk.u = *reinterpret_cast<const uint2*>(g_mix + e * 256 + base);
            float2 f0 = __half22float2(pk.h[0]);
            float2 f1 = __half22float2(pk.h[1]);
            *reinterpret_cast<float4*>(M + base) = make_float4(f0.x, f0.y, f1.x, f1.y);
        }
        {
            union { uint2 u; __half2 h[2]; } pk;
            pk.u = *reinterpret_cast<const uint2*>(g_v + snd * 192 + l * 4);
            float2 f0 = __half22float2(pk.h[0]);
            float2 f1 = __half22float2(pk.h[1]);
            *reinterpret_cast<float4*>(V + l * 4) = make_float4(f0.x, f0.y, f1.x, f1.y);
            if (l < 16) {
                pk.u = *reinterpret_cast<const uint2*>(g_v + snd * 192 + 128 + l * 4);
                f0 = __half22float2(pk.h[0]);
                f1 = __half22float2(pk.h[1]);
                *reinterpret_cast<float4*>(V + 128 + l * 4) = make_float4(f0.x, f0.y, f1.x, f1.y);
            }
        }
        if (l < 16) {
            union { uint2 u; __half2 h[2]; } pk;
            pk.u = *reinterpret_cast<const uint2*>(g_s + snd * 64 + l * 4);
            float2 f0 = __half22float2(pk.h[0]);
            float2 f1 = __half22float2(pk.h[1]);
            *reinterpret_cast<float4*>(S + l * 4) = make_float4(f0.x, f0.y, f1.x, f1.y);
        }
        if (l == 0)
            *reinterpret_cast<float4*>(Yp) = *reinterpret_cast<const float4*>(g_y + e * 4);
        __syncwarp();

#pragma unroll
        for (int j = 0; j < 4; j++) {
            int o = l + 32 * j;  // 0..127
            if (o < 16) {
                int c = o * 4;
                red4(g_agg_s + rcv * 128 + c,
                     S[c] * M[c], S[c + 1] * M[c + 1],
                     S[c + 2] * M[c + 2], S[c + 3] * M[c + 3]);
            } else if (o < 32) {
                int c = (o - 16) * 4;
                float y0 = Yp[0], y1 = Yp[1], y2 = Yp[2];
                float v[4];
#pragma unroll
                for (int t = 0; t < 4; t++) {
                    int cc = c + t;
                    v[t] = (V[cc * 3] * y0 + V[cc * 3 + 1] * y1 + V[cc * 3 + 2] * y2)
                           * INV_SQRT3 * M[64 + cc];
                }
                red4(g_agg_s + rcv * 128 + 64 + c, v[0], v[1], v[2], v[3]);
            } else {
                int q = o - 32;          // 0..95
                int m = q >> 5, cb = q & 31;
                int c2 = cb * 4;
                float v[4];
                if (c2 < 64) {
#pragma unroll
                    for (int t = 0; t < 4; t++)
                        v[t] = V[(c2 + t) * 3 + m] * M[128 + c2 + t];
                } else {
                    int c = c2 - 64;
                    float ym = Yp[m];
#pragma unroll
                    for (int t = 0; t < 4; t++)
                        v[t] = S[c + t] * ym * M[192 + c + t];
                }
                red4(g_agg_v + rcv * 384 + m * 128 + c2, v[0], v[1], v[2], v[3]);
            }
        }
        __syncwarp();
    }
}

// ---------------- kernel: final down-projection + skip + gating + output ----------------
__global__ void __launch_bounds__(256) k_final(const float* __restrict__ Wds,
                                               const float* __restrict__ Wdv,
                                               float* __restrict__ out) {
    extern __shared__ float sm[];
    float* sWs = sm;            // 16384
    float* sWv = sm + 16384;    // 8192
    float* sBuf = sm + 24576;   // 8 * 520
    int tid = threadIdx.x, wid = tid >> 5, l = tid & 31;
    for (int i = tid; i < 16384; i += 256) sWs[i] = Wds[i];
    for (int i = tid; i < 8192; i += 256) sWv[i] = Wdv[i];
    __syncthreads();
    float* As = sBuf + wid * 520;
    float* Av = As + 128;
    const float INV = 0.25f;
    int nwarp = gridDim.x * 8;
    for (int n = blockIdx.x * 8 + wid; n < NN; n += nwarp) {
#pragma unroll
        for (int q = 0; q < 4; q++) As[l + 32 * q] = g_agg_s[n * 128 + l + 32 * q];
#pragma unroll
        for (int q = 0; q < 12; q++) Av[l + 32 * q] = g_agg_v[n * 384 + l + 32 * q];
        __syncwarp();
        float a0 = 0.f, a1 = 0.f, a2 = 0.f, a3 = 0.f;
#pragma unroll 4
        for (int k = 0; k < 128; k++) {
            float x = As[k];
            const float* w = sWs + k * 128;
            a0 = fmaf(x, w[l], a0);
            a1 = fmaf(x, w[l + 32], a1);
            a2 = fmaf(x, w[l + 64], a2);
            a3 = fmaf(x, w[l + 96], a3);
        }
        float os0 = INV * a0 + g_skip_s[n * 128 + l];
        float os1 = INV * a1 + g_skip_s[n * 128 + l + 32];
        float os2 = INV * a2 + g_skip_s[n * 128 + l + 64];
        float os3 = INV * a3 + g_skip_s[n * 128 + l + 96];
        float scal0 = swishf(os0), scal1 = swishf(os1);
        float gate0 = swishf(os2), gate1 = swishf(os3);
        float v0[3] = {0.f, 0.f, 0.f}, v1[3] = {0.f, 0.f, 0.f};
#pragma unroll 4
        for (int k = 0; k < 128; k++) {
            float w0 = sWv[k * 64 + l], w1 = sWv[k * 64 + l + 32];
#pragma unroll
            for (int m = 0; m < 3; m++) {
                float a = Av[m * 128 + k];
                v0[m] = fmaf(a, w0, v0[m]);
                v1[m] = fmaf(a, w1, v1[m]);
            }
        }
        out[n * 256 + l] = scal0;
        out[n * 256 + l + 32] = scal1;
#pragma unroll
        for (int m = 0; m < 3; m++) {
            float ov0 = INV * v0[m] + g_skip_v[n * 192 + l * 3 + m];
            float ov1 = INV * v1[m] + g_skip_v[n * 192 + (l + 32) * 3 + m];
            out[n * 256 + 64 + l * 3 + m] = ov0 * gate0;
            out[n * 256 + 64 + (l + 32) * 3 + m] = ov1 * gate1;
        }
        __syncwarp();
    }
}

// ---------------- launch ----------------
extern "C" void kernel_launch(void* const* d_in, const int* in_sizes, int n_in,
                              void* d_out, int out_size) {
    const float* vectors      = (const float*)d_in[0];
    const float* node_scalars = (const float*)d_in[1];
    const float* node_vectors = (const float*)d_in[2];
    const int*   node_specie  = (const int*)d_in[3];
    const int*   senders      = (const int*)d_in[4];
    const int*   receivers    = (const int*)d_in[5];
    const float* W_skip_s     = (const float*)d_in[6];
    const float* W_skip_v     = (const float*)d_in[7];
    const float* W_up_s       = (const float*)d_in[8];
    const float* W_up_v       = (const float*)d_in[9];
    const float* W_mlp0       = (const float*)d_in[10];
    const float* W_mlp1       = (const float*)d_in[11];
    const float* W_mlp2       = (const float*)d_in[12];
    const float* W_down_s     = (const float*)d_in[13];
    const float* W_down_v     = (const float*)d_in[14];
    float* out = (float*)d_out;

    const int UP_SMEM    = (8192 + 8 * 256) * 4;            // 40 KB
    const int SKIP_SMEM  = (49152 + 8 * 256) * 4;           // 200 KB
    const int MLP_SMEM   = MLP_SMEM_FLOATS * 4;             // ~78.5 KB -> 2 blocks/SM
    const int FINAL_SMEM = (24576 + 8 * 520) * 4;           // ~114.5 KB

    cudaFuncSetAttribute(k_skip,  cudaFuncAttributeMaxDynamicSharedMemorySize, SKIP_SMEM);
    cudaFuncSetAttribute(k_mlp,   cudaFuncAttributeMaxDynamicSharedMemorySize, MLP_SMEM);
    cudaFuncSetAttribute(k_final, cudaFuncAttributeMaxDynamicSharedMemorySize, FINAL_SMEM);

    k_zero<<<2048, 256>>>();
    k_up<<<512, 256, UP_SMEM>>>(node_scalars, node_vectors, W_up_s, W_up_v);
    k_skip<<<296, 256, SKIP_SMEM>>>(node_scalars, node_vectors, node_specie, W_skip_s, W_skip_v);
    k_mlp<<<296, 256, MLP_SMEM>>>(vectors, W_mlp0, W_mlp1, W_mlp2);
    k_scatter<<<2960, 256>>>(senders, receivers);
    k_final<<<296, 256, FINAL_SMEM>>>(W_down_s, W_down_v, out);
}